// round 9
// baseline (speedup 1.0000x reference)
#include <cuda_runtime.h>
#include <math.h>

#define N_NODES 50000
#define E_EDGES 1600000
#define HC      32
#define G_GRAPHS 512
#define STRIDE  96          // padded CSR bucket; indeg ~ Poisson(32), P(>=88) ~ 1e-16

// ---------------- static scratch ----------------
__device__ int   g_cnt   [N_NODES];          // in-degree == bucket fill count
__device__ int   g_outdeg[N_NODES];
__device__ int   g_col   [N_NODES * STRIDE]; // buckets of source ROW OFFSETS (s*HC), self-padded
__device__ float g_xl [N_NODES * HC];
__device__ float g_xr [N_NODES * HC];
__device__ float g_xl2[N_NODES * HC];
__device__ float g_xr2[N_NODES * HC];
__device__ float g_sums[G_GRAPHS * HC];

__device__ __forceinline__ float ex2(float x) {
    float r; asm("ex2.approx.f32 %0, %1;" : "=f"(r) : "f"(x)); return r;
}

// ---------------- kernels ----------------
__global__ void zero_kernel() {
    int i = blockIdx.x * blockDim.x + threadIdx.x;
    if (i < N_NODES) { g_cnt[i] = 0; g_outdeg[i] = 0; }
    if (i < G_GRAPHS * HC) g_sums[i] = 0.f;
}

// fused CSR build: bucket scatter (pos atomic == indeg count) + outdeg; 4 edges/thread.
// Stores s*HC (row offset) so conv kernels skip the multiply.
__global__ void build_kernel(const int* __restrict__ ei) {
    int e0 = (blockIdx.x * blockDim.x + threadIdx.x) * 4;
    if (e0 >= E_EDGES) return;
    int4 s = *(const int4*)(ei + e0);
    int4 d = *(const int4*)(ei + E_EDGES + e0);
    int p0 = atomicAdd(&g_cnt[d.x], 1);
    int p1 = atomicAdd(&g_cnt[d.y], 1);
    int p2 = atomicAdd(&g_cnt[d.z], 1);
    int p3 = atomicAdd(&g_cnt[d.w], 1);
    g_col[d.x * STRIDE + p0] = s.x * HC;
    g_col[d.y * STRIDE + p1] = s.y * HC;
    g_col[d.z * STRIDE + p2] = s.z * HC;
    g_col[d.w * STRIDE + p3] = s.w * HC;
    atomicAdd(&g_outdeg[s.x], 1); atomicAdd(&g_outdeg[s.y], 1);
    atomicAdd(&g_outdeg[s.z], 1); atomicAdd(&g_outdeg[s.w], 1);
}

// pad slots [cnt, cnt+16) with the node's own row offset -> pad edges have w=1, v=self,
// which the conv epilogue subtracts exactly. Covers loop reads + one prefetch-ahead.
__global__ void pad_kernel() {
    int node = blockIdx.x * blockDim.x + threadIdx.x;
    if (node >= N_NODES) return;
    int cnt  = g_cnt[node];
    int base = node * STRIDE;
    int v    = node * HC;
    int end  = min(cnt + 16, STRIDE);
    for (int i = cnt; i < end; i++) g_col[base + i] = v;
}

// x0 = [1, deg, rand]; xl/xr = x0 @ W^T + b. warp per node, lane = out channel
__global__ void feat_lin1_kernel(const float* __restrict__ rand_feat,
                                 const float* __restrict__ Wl, const float* __restrict__ bl,
                                 const float* __restrict__ Wr, const float* __restrict__ br) {
    int idx = blockIdx.x * blockDim.x + threadIdx.x;
    int node = idx >> 5, lane = idx & 31;
    if (node >= N_NODES) return;
    float x1 = (float)(g_outdeg[node] + g_cnt[node]);
    float x2 = rand_feat[node];
    g_xl[idx] = Wl[lane * 3 + 0] + Wl[lane * 3 + 1] * x1 + Wl[lane * 3 + 2] * x2 + bl[lane];
    g_xr[idx] = Wr[lane * 3 + 0] + Wr[lane * 3 + 1] * x1 + Wr[lane * 3 + 2] * x2 + br[lane];
}

// GATv2 conv: warp per destination node, 4 edge-subgroups of 8 lanes,
// lane holds 4 channels (float4) -> 128B row in ONE LDG.128 per edge.
// LeakyReLU(m)*att*log2e = a06*m + a04*|m|; Sum(a06*xr) hoisted; -pself folded
// into the score seed so w = ex2(p) directly.
// Branch-free edge loop over roundup8(cnt) slots (pads = self row, w=1, v=self),
// corrected exactly in the epilogue: denom -= padcnt, acc -= padcnt*vs.
// Per-head score reduce = shfl xor 1,2. Cross-subgroup combine = shfl xor 8,16.
// MODE 0: reads g_xl/g_xr, fused 32->32 x2 linear (smem transpose) -> g_xl2/g_xr2.
// MODE 1: reads g_xl2/g_xr2, fused mean-pool atomicAdd into g_sums.
template<int MODE>
__global__ void __launch_bounds__(256, 5)
conv_kernel(const float* __restrict__ att, const float* __restrict__ bias,
            const float* __restrict__ Wl, const float* __restrict__ bl,
            const float* __restrict__ Wr, const float* __restrict__ br,
            const int* __restrict__ batch) {
    const float* __restrict__ xl = (MODE == 0) ? g_xl : g_xl2;
    const float* __restrict__ xr = (MODE == 0) ? g_xr : g_xr2;
    const unsigned FULL = 0xffffffffu;

    __shared__ float sWl[32 * 36];
    __shared__ float sWr[32 * 36];
    __shared__ float so [8 * 32];
    if (MODE == 0) {
        for (int i = threadIdx.x; i < 1024; i += blockDim.x) {
            int r = i >> 5, c = i & 31;
            sWl[r * 36 + c] = Wl[i];
            sWr[r * 36 + c] = Wr[i];
        }
        __syncthreads();
    }
    int gidx = blockIdx.x * blockDim.x + threadIdx.x;
    int node = gidx >> 5, lane = gidx & 31;
    if (node >= N_NODES) return;
    const int sub = lane >> 3;     // edge slot 0..3
    const int q   = lane & 7;      // channel quad 0..7
    const int wlocal = (threadIdx.x >> 5);
    const int nodeHC = node * HC;

    const float LOG2E = 1.4426950408889634f;
    const float4 attr = *(const float4*)(att + q * 4);
    float4 a06, a04;
    a06.x = 0.6f * LOG2E * attr.x; a04.x = 0.4f * LOG2E * attr.x;
    a06.y = 0.6f * LOG2E * attr.y; a04.y = 0.4f * LOG2E * attr.y;
    a06.z = 0.6f * LOG2E * attr.z; a04.z = 0.4f * LOG2E * attr.z;
    a06.w = 0.6f * LOG2E * attr.w; a04.w = 0.4f * LOG2E * attr.w;

    const float4 xr4 = *(const float4*)(xr + nodeHC + q * 4);
    // hoisted per-node term: sum_c a06_c * xr_c (this lane's 4 channels)
    float base = a06.x * xr4.x + a06.y * xr4.y + a06.z * xr4.z + a06.w * xr4.w;

    // self loop + softmax baseline pself (log2-scaled, per head)
    const float4 vs4 = *(const float4*)(xl + nodeHC + q * 4);
    float ps, m;
    ps = fmaf(a06.x, vs4.x, base);
    m = vs4.x + xr4.x; ps = fmaf(a04.x, fabsf(m), ps);
    m = vs4.y + xr4.y; ps = fmaf(a06.y, vs4.y, ps); ps = fmaf(a04.y, fabsf(m), ps);
    m = vs4.z + xr4.z; ps = fmaf(a06.z, vs4.z, ps); ps = fmaf(a04.z, fabsf(m), ps);
    m = vs4.w + xr4.w; ps = fmaf(a06.w, vs4.w, ps); ps = fmaf(a04.w, fabsf(m), ps);
    ps += __shfl_xor_sync(FULL, ps, 1);
    ps += __shfl_xor_sync(FULL, ps, 2);
    // fold base and -pself/4 into the per-edge score seed
    const float seed = base - 0.25f * ps;

    float wsf = (sub == 0) ? 1.f : 0.f;   // self weight: ex2(ps - ps) = 1
    float denom = wsf;
    float4 acc = make_float4(vs4.x * wsf, vs4.y * wsf, vs4.z * wsf, vs4.w * wsf);

    const int beg = nodeHC * (STRIDE / HC);   // node * STRIDE
    const int cnt = g_cnt[node];
    const int rnd = (cnt + 7) & ~7;           // roundup8; slots [cnt, rnd) are self pads
    const float padcnt = (float)(rnd - cnt);
    const int endp = beg + rnd;

    // unconditional prefetch (pad region guarantees defined values)
    int c0 = __ldg(g_col + beg + sub);
    int c1 = __ldg(g_col + beg + 4 + sub);

    for (int e = beg; e < endp; e += 8) {
        int s0 = c0, s1 = c1;
        c0 = __ldg(g_col + e + 8 + sub);
        c1 = __ldg(g_col + e + 12 + sub);

        float4 a0 = *(const float4*)(xl + s0 + q * 4);
        float4 a1 = *(const float4*)(xl + s1 + q * 4);

        float p0, p1, t;
        p0 = fmaf(a06.x, a0.x, seed);
        t = a0.x + xr4.x; p0 = fmaf(a04.x, fabsf(t), p0);
        t = a0.y + xr4.y; p0 = fmaf(a06.y, a0.y, p0); p0 = fmaf(a04.y, fabsf(t), p0);
        t = a0.z + xr4.z; p0 = fmaf(a06.z, a0.z, p0); p0 = fmaf(a04.z, fabsf(t), p0);
        t = a0.w + xr4.w; p0 = fmaf(a06.w, a0.w, p0); p0 = fmaf(a04.w, fabsf(t), p0);
        p1 = fmaf(a06.x, a1.x, seed);
        t = a1.x + xr4.x; p1 = fmaf(a04.x, fabsf(t), p1);
        t = a1.y + xr4.y; p1 = fmaf(a06.y, a1.y, p1); p1 = fmaf(a04.y, fabsf(t), p1);
        t = a1.z + xr4.z; p1 = fmaf(a06.z, a1.z, p1); p1 = fmaf(a04.z, fabsf(t), p1);
        t = a1.w + xr4.w; p1 = fmaf(a06.w, a1.w, p1); p1 = fmaf(a04.w, fabsf(t), p1);

        p0 += __shfl_xor_sync(FULL, p0, 1);
        p0 += __shfl_xor_sync(FULL, p0, 2);
        p1 += __shfl_xor_sync(FULL, p1, 1);
        p1 += __shfl_xor_sync(FULL, p1, 2);
        float w0 = ex2(p0);
        float w1 = ex2(p1);
        denom += w0 + w1;
        acc.x = fmaf(w0, a0.x, acc.x); acc.y = fmaf(w0, a0.y, acc.y);
        acc.z = fmaf(w0, a0.z, acc.z); acc.w = fmaf(w0, a0.w, acc.w);
        acc.x = fmaf(w1, a1.x, acc.x); acc.y = fmaf(w1, a1.y, acc.y);
        acc.z = fmaf(w1, a1.z, acc.z); acc.w = fmaf(w1, a1.w, acc.w);
    }

    // combine the 4 edge subgroups (q invariant under xor 8/16 -> head-safe)
#pragma unroll
    for (int off = 8; off <= 16; off <<= 1) {
        acc.x += __shfl_xor_sync(FULL, acc.x, off);
        acc.y += __shfl_xor_sync(FULL, acc.y, off);
        acc.z += __shfl_xor_sync(FULL, acc.z, off);
        acc.w += __shfl_xor_sync(FULL, acc.w, off);
        denom += __shfl_xor_sync(FULL, denom, off);
    }

    // exact pad correction: each pad edge contributed w=1, v=vs
    denom -= padcnt;
    acc.x = fmaf(-padcnt, vs4.x, acc.x);
    acc.y = fmaf(-padcnt, vs4.y, acc.y);
    acc.z = fmaf(-padcnt, vs4.z, acc.z);
    acc.w = fmaf(-padcnt, vs4.w, acc.w);

    const float4 b4 = *(const float4*)(bias + q * 4);
    float rd = __fdividef(1.f, denom + 1e-16f);
    float4 o4;
    o4.x = fmaf(acc.x, rd, b4.x);
    o4.y = fmaf(acc.y, rd, b4.y);
    o4.z = fmaf(acc.z, rd, b4.z);
    o4.w = fmaf(acc.w, rd, b4.w);
    o4.x = o4.x > 0.f ? o4.x : (__expf(o4.x) - 1.f);
    o4.y = o4.y > 0.f ? o4.y : (__expf(o4.y) - 1.f);
    o4.z = o4.z > 0.f ? o4.z : (__expf(o4.z) - 1.f);
    o4.w = o4.w > 0.f ? o4.w : (__expf(o4.w) - 1.f);

    if (MODE == 0) {
        // fused lin2 via warp-private smem transpose (no shuffles)
        if (sub == 0) *(float4*)&so[wlocal * 32 + q * 4] = o4;
        __syncwarp(FULL);
        float aL = bl[lane], aR = br[lane];
#pragma unroll
        for (int ch = 0; ch < 8; ch++) {
            float4 ov = *(const float4*)&so[wlocal * 32 + ch * 4];   // broadcast
            float4 wl = *(const float4*)&sWl[lane * 36 + ch * 4];    // conflict-free
            float4 wr = *(const float4*)&sWr[lane * 36 + ch * 4];
            aL = fmaf(ov.x, wl.x, aL); aL = fmaf(ov.y, wl.y, aL);
            aL = fmaf(ov.z, wl.z, aL); aL = fmaf(ov.w, wl.w, aL);
            aR = fmaf(ov.x, wr.x, aR); aR = fmaf(ov.y, wr.y, aR);
            aR = fmaf(ov.z, wr.z, aR); aR = fmaf(ov.w, wr.w, aR);
        }
        g_xl2[nodeHC + lane] = aL;
        g_xr2[nodeHC + lane] = aR;
    } else {
        if (sub == 0) {
            int g = batch[node];
            float* dst = &g_sums[g * HC + q * 4];
            atomicAdd(dst + 0, o4.x);
            atomicAdd(dst + 1, o4.y);
            atomicAdd(dst + 2, o4.z);
            atomicAdd(dst + 3, o4.w);
        }
    }
}

__device__ __forceinline__ int lbound(const int* __restrict__ a, int key) {
    int lo = 0, hi = N_NODES;
    while (lo < hi) {
        int mid = (lo + hi) >> 1;
        if (a[mid] < key) lo = mid + 1; else hi = mid;
    }
    return lo;
}

// one warp per graph: counts via binary search on sorted batch, mean pool, fc, log_softmax
__global__ void head_kernel(const int* __restrict__ batch,
                            const float* __restrict__ Wfc, const float* __restrict__ bfc,
                            float* __restrict__ out) {
    int g = blockIdx.x;
    int lane = threadIdx.x;
    int lo = lbound(batch, g);
    int hi = lbound(batch, g + 1);
    float cnt = fmaxf((float)(hi - lo), 1.f);
    float pooled = g_sums[g * HC + lane] / cnt;
    float p0 = pooled * Wfc[lane];
    float p1 = pooled * Wfc[HC + lane];
#pragma unroll
    for (int off = 16; off; off >>= 1) {
        p0 += __shfl_xor_sync(0xffffffffu, p0, off);
        p1 += __shfl_xor_sync(0xffffffffu, p1, off);
    }
    if (lane == 0) {
        float l0 = p0 + bfc[0];
        float l1 = p1 + bfc[1];
        float mx = fmaxf(l0, l1);
        float lse = mx + logf(expf(l0 - mx) + expf(l1 - mx));
        out[g * 2 + 0] = l0 - lse;
        out[g * 2 + 1] = l1 - lse;
    }
}

// ---------------- launch ----------------
extern "C" void kernel_launch(void* const* d_in, const int* in_sizes, int n_in,
                              void* d_out, int out_size) {
    const int*   ei        = (const int*)  d_in[0];
    const int*   batch     = (const int*)  d_in[1];
    const float* rand_feat = (const float*)d_in[2];
    const float* W1l  = (const float*)d_in[3];
    const float* b1l  = (const float*)d_in[4];
    const float* W1r  = (const float*)d_in[5];
    const float* b1r  = (const float*)d_in[6];
    const float* att1 = (const float*)d_in[7];
    const float* bias1= (const float*)d_in[8];
    const float* W2l  = (const float*)d_in[9];
    const float* b2l  = (const float*)d_in[10];
    const float* W2r  = (const float*)d_in[11];
    const float* b2r  = (const float*)d_in[12];
    const float* att2 = (const float*)d_in[13];
    const float* bias2= (const float*)d_in[14];
    const float* Wfc  = (const float*)d_in[15];
    const float* bfc  = (const float*)d_in[16];
    float* out = (float*)d_out;

    zero_kernel <<<(N_NODES + 255) / 256, 256>>>();
    build_kernel<<<(E_EDGES / 4 + 255) / 256, 256>>>(ei);
    pad_kernel  <<<(N_NODES + 255) / 256, 256>>>();

    feat_lin1_kernel<<<(N_NODES * HC + 255) / 256, 256>>>(rand_feat, W1l, b1l, W1r, b1r);

    conv_kernel<0><<<(N_NODES * HC + 255) / 256, 256>>>(
        att1, bias1, W2l, b2l, W2r, b2r, nullptr);
    conv_kernel<1><<<(N_NODES * HC + 255) / 256, 256>>>(
        att2, bias2, nullptr, nullptr, nullptr, nullptr, batch);

    head_kernel<<<G_GRAPHS, 32>>>(batch, Wfc, bfc, out);
}

// round 10
// speedup vs baseline: 1.0751x; 1.0751x over previous
#include <cuda_runtime.h>
#include <math.h>

#define N_NODES 50000
#define E_EDGES 1600000
#define HC      32
#define G_GRAPHS 512
#define STRIDE  96          // padded CSR bucket; indeg ~ Poisson(32), P(>=96) ~ e^-40

// ---------------- static scratch ----------------
__device__ int   g_cnt   [N_NODES];          // in-degree == bucket fill count
__device__ int   g_outdeg[N_NODES];
__device__ int   g_col   [N_NODES * STRIDE]; // buckets of source ROW OFFSETS (s*HC)
__device__ float g_xl [N_NODES * HC];
__device__ float g_xr [N_NODES * HC];
__device__ float g_xl2[N_NODES * HC];
__device__ float g_xr2[N_NODES * HC];
__device__ float g_sums[G_GRAPHS * HC];

__device__ __forceinline__ float ex2(float x) {
    float r; asm("ex2.approx.f32 %0, %1;" : "=f"(r) : "f"(x)); return r;
}

// ---------------- kernels ----------------
__global__ void zero_kernel() {
    int i = blockIdx.x * blockDim.x + threadIdx.x;
    if (i < N_NODES) { g_cnt[i] = 0; g_outdeg[i] = 0; }
    if (i < G_GRAPHS * HC) g_sums[i] = 0.f;
}

// fused CSR build: bucket scatter (pos atomic == indeg count) + outdeg; 4 edges/thread.
// Stores s*HC (row offset) so conv kernels skip the multiply.
__global__ void build_kernel(const int* __restrict__ ei) {
    int e0 = (blockIdx.x * blockDim.x + threadIdx.x) * 4;
    if (e0 >= E_EDGES) return;
    int4 s = *(const int4*)(ei + e0);
    int4 d = *(const int4*)(ei + E_EDGES + e0);
    int p0 = atomicAdd(&g_cnt[d.x], 1);
    int p1 = atomicAdd(&g_cnt[d.y], 1);
    int p2 = atomicAdd(&g_cnt[d.z], 1);
    int p3 = atomicAdd(&g_cnt[d.w], 1);
    g_col[d.x * STRIDE + p0] = s.x * HC;
    g_col[d.y * STRIDE + p1] = s.y * HC;
    g_col[d.z * STRIDE + p2] = s.z * HC;
    g_col[d.w * STRIDE + p3] = s.w * HC;
    atomicAdd(&g_outdeg[s.x], 1); atomicAdd(&g_outdeg[s.y], 1);
    atomicAdd(&g_outdeg[s.z], 1); atomicAdd(&g_outdeg[s.w], 1);
}

// x0 = [1, deg, rand]; xl/xr = x0 @ W^T + b. warp per node, lane = out channel
__global__ void feat_lin1_kernel(const float* __restrict__ rand_feat,
                                 const float* __restrict__ Wl, const float* __restrict__ bl,
                                 const float* __restrict__ Wr, const float* __restrict__ br) {
    int idx = blockIdx.x * blockDim.x + threadIdx.x;
    int node = idx >> 5, lane = idx & 31;
    if (node >= N_NODES) return;
    float x1 = (float)(g_outdeg[node] + g_cnt[node]);
    float x2 = rand_feat[node];
    g_xl[idx] = Wl[lane * 3 + 0] + Wl[lane * 3 + 1] * x1 + Wl[lane * 3 + 2] * x2 + bl[lane];
    g_xr[idx] = Wr[lane * 3 + 0] + Wr[lane * 3 + 1] * x1 + Wr[lane * 3 + 2] * x2 + br[lane];
}

// GATv2 conv: warp per destination node, 4 edge-subgroups of 8 lanes,
// lane holds 4 channels (float4) -> 128B row in ONE LDG.128 per edge.
// Score decomposition (log2-scaled): LeakyReLU(m)*att = 0.6*a*(m + (2/3)|m|);
// with a06 = 0.6*log2e*att, per channel: m=FADD, u=FFMA(2/3-imm,|m|,v), p=FFMA(a06,u,p).
// Sum(a06*xr) hoisted per node; -pself folded into the score seed -> w = ex2(p).
// Per-head score reduce = shfl xor 1,2. Cross-subgroup combine = shfl xor 8,16.
// MODE 0: reads g_xl/g_xr, fused 32->32 x2 linear (smem transpose) -> g_xl2/g_xr2.
// MODE 1: reads g_xl2/g_xr2, fused mean-pool atomicAdd into g_sums.
template<int MODE>
__global__ void __launch_bounds__(256, 6)
conv_kernel(const float* __restrict__ att, const float* __restrict__ bias,
            const float* __restrict__ Wl, const float* __restrict__ bl,
            const float* __restrict__ Wr, const float* __restrict__ br,
            const int* __restrict__ batch) {
    const float* __restrict__ xl = (MODE == 0) ? g_xl : g_xl2;
    const float* __restrict__ xr = (MODE == 0) ? g_xr : g_xr2;
    const unsigned FULL = 0xffffffffu;
    const float TWO3 = 0.66666667f;

    __shared__ float sWl[32 * 36];
    __shared__ float sWr[32 * 36];
    __shared__ float so [8 * 32];
    if (MODE == 0) {
        for (int i = threadIdx.x; i < 1024; i += blockDim.x) {
            int r = i >> 5, c = i & 31;
            sWl[r * 36 + c] = Wl[i];
            sWr[r * 36 + c] = Wr[i];
        }
        __syncthreads();
    }
    int gidx = blockIdx.x * blockDim.x + threadIdx.x;
    int node = gidx >> 5, lane = gidx & 31;
    if (node >= N_NODES) return;
    const int sub = lane >> 3;     // edge slot 0..3
    const int q   = lane & 7;      // channel quad 0..7
    const int wlocal = (threadIdx.x >> 5);
    const int nodeHC = node * HC;

    const float LOG2E = 1.4426950408889634f;
    float4 a06 = *(const float4*)(att + q * 4);
    a06.x *= 0.6f * LOG2E; a06.y *= 0.6f * LOG2E;
    a06.z *= 0.6f * LOG2E; a06.w *= 0.6f * LOG2E;

    const float4 xr4 = *(const float4*)(xr + nodeHC + q * 4);
    // hoisted per-node term: sum_c a06_c * xr_c (this lane's 4 channels)
    float base = a06.x * xr4.x + a06.y * xr4.y + a06.z * xr4.z + a06.w * xr4.w;

    // self loop + softmax baseline pself (log2-scaled, per head)
    const float4 vs4 = *(const float4*)(xl + nodeHC + q * 4);
    float ps = base, m, u;
    m = vs4.x + xr4.x; u = fmaf(TWO3, fabsf(m), vs4.x); ps = fmaf(a06.x, u, ps);
    m = vs4.y + xr4.y; u = fmaf(TWO3, fabsf(m), vs4.y); ps = fmaf(a06.y, u, ps);
    m = vs4.z + xr4.z; u = fmaf(TWO3, fabsf(m), vs4.z); ps = fmaf(a06.z, u, ps);
    m = vs4.w + xr4.w; u = fmaf(TWO3, fabsf(m), vs4.w); ps = fmaf(a06.w, u, ps);
    ps += __shfl_xor_sync(FULL, ps, 1);
    ps += __shfl_xor_sync(FULL, ps, 2);
    // fold base and -pself/4 into the per-edge score seed
    const float seed = base - 0.25f * ps;

    float wsf = (sub == 0) ? 1.f : 0.f;   // self weight: ex2(ps - ps) = 1
    float denom = wsf;
    float4 acc = make_float4(vs4.x * wsf, vs4.y * wsf, vs4.z * wsf, vs4.w * wsf);

    const int beg = node * STRIDE;
    const int end = beg + g_cnt[node];

    int c0 = (beg + sub     < end) ? __ldg(g_col + beg + sub)     : nodeHC;
    int c1 = (beg + 4 + sub < end) ? __ldg(g_col + beg + 4 + sub) : nodeHC;

    for (int e = beg; e < end; e += 8) {
        bool ok0 = (e + sub)     < end;
        bool ok1 = (e + 4 + sub) < end;
        int s0 = c0, s1 = c1;
        int n0 = e + 8 + sub, n1 = e + 12 + sub;
        c0 = (n0 < end) ? __ldg(g_col + n0) : nodeHC;
        c1 = (n1 < end) ? __ldg(g_col + n1) : nodeHC;

        float4 a0 = *(const float4*)(xl + s0 + q * 4);
        float4 a1 = *(const float4*)(xl + s1 + q * 4);

        float p0 = seed, p1 = seed, t, v;
        t = a0.x + xr4.x; v = fmaf(TWO3, fabsf(t), a0.x); p0 = fmaf(a06.x, v, p0);
        t = a0.y + xr4.y; v = fmaf(TWO3, fabsf(t), a0.y); p0 = fmaf(a06.y, v, p0);
        t = a0.z + xr4.z; v = fmaf(TWO3, fabsf(t), a0.z); p0 = fmaf(a06.z, v, p0);
        t = a0.w + xr4.w; v = fmaf(TWO3, fabsf(t), a0.w); p0 = fmaf(a06.w, v, p0);
        t = a1.x + xr4.x; v = fmaf(TWO3, fabsf(t), a1.x); p1 = fmaf(a06.x, v, p1);
        t = a1.y + xr4.y; v = fmaf(TWO3, fabsf(t), a1.y); p1 = fmaf(a06.y, v, p1);
        t = a1.z + xr4.z; v = fmaf(TWO3, fabsf(t), a1.z); p1 = fmaf(a06.z, v, p1);
        t = a1.w + xr4.w; v = fmaf(TWO3, fabsf(t), a1.w); p1 = fmaf(a06.w, v, p1);

        p0 += __shfl_xor_sync(FULL, p0, 1);
        p0 += __shfl_xor_sync(FULL, p0, 2);
        p1 += __shfl_xor_sync(FULL, p1, 1);
        p1 += __shfl_xor_sync(FULL, p1, 2);
        float w0 = ok0 ? ex2(p0) : 0.f;
        float w1 = ok1 ? ex2(p1) : 0.f;
        denom += w0 + w1;
        acc.x = fmaf(w0, a0.x, acc.x); acc.y = fmaf(w0, a0.y, acc.y);
        acc.z = fmaf(w0, a0.z, acc.z); acc.w = fmaf(w0, a0.w, acc.w);
        acc.x = fmaf(w1, a1.x, acc.x); acc.y = fmaf(w1, a1.y, acc.y);
        acc.z = fmaf(w1, a1.z, acc.z); acc.w = fmaf(w1, a1.w, acc.w);
    }

    // combine the 4 edge subgroups (q invariant under xor 8/16 -> head-safe)
#pragma unroll
    for (int off = 8; off <= 16; off <<= 1) {
        acc.x += __shfl_xor_sync(FULL, acc.x, off);
        acc.y += __shfl_xor_sync(FULL, acc.y, off);
        acc.z += __shfl_xor_sync(FULL, acc.z, off);
        acc.w += __shfl_xor_sync(FULL, acc.w, off);
        denom += __shfl_xor_sync(FULL, denom, off);
    }

    const float4 b4 = *(const float4*)(bias + q * 4);
    float rd = __fdividef(1.f, denom + 1e-16f);
    float4 o4;
    o4.x = fmaf(acc.x, rd, b4.x);
    o4.y = fmaf(acc.y, rd, b4.y);
    o4.z = fmaf(acc.z, rd, b4.z);
    o4.w = fmaf(acc.w, rd, b4.w);
    o4.x = o4.x > 0.f ? o4.x : (__expf(o4.x) - 1.f);
    o4.y = o4.y > 0.f ? o4.y : (__expf(o4.y) - 1.f);
    o4.z = o4.z > 0.f ? o4.z : (__expf(o4.z) - 1.f);
    o4.w = o4.w > 0.f ? o4.w : (__expf(o4.w) - 1.f);

    if (MODE == 0) {
        // fused lin2 via warp-private smem transpose (no shuffles)
        if (sub == 0) *(float4*)&so[wlocal * 32 + q * 4] = o4;
        __syncwarp(FULL);
        float aL = bl[lane], aR = br[lane];
#pragma unroll
        for (int ch = 0; ch < 8; ch++) {
            float4 ov = *(const float4*)&so[wlocal * 32 + ch * 4];   // broadcast
            float4 wl = *(const float4*)&sWl[lane * 36 + ch * 4];    // conflict-free
            float4 wr = *(const float4*)&sWr[lane * 36 + ch * 4];
            aL = fmaf(ov.x, wl.x, aL); aL = fmaf(ov.y, wl.y, aL);
            aL = fmaf(ov.z, wl.z, aL); aL = fmaf(ov.w, wl.w, aL);
            aR = fmaf(ov.x, wr.x, aR); aR = fmaf(ov.y, wr.y, aR);
            aR = fmaf(ov.z, wr.z, aR); aR = fmaf(ov.w, wr.w, aR);
        }
        g_xl2[nodeHC + lane] = aL;
        g_xr2[nodeHC + lane] = aR;
    } else {
        if (sub == 0) {
            int g = batch[node];
            float* dst = &g_sums[g * HC + q * 4];
            atomicAdd(dst + 0, o4.x);
            atomicAdd(dst + 1, o4.y);
            atomicAdd(dst + 2, o4.z);
            atomicAdd(dst + 3, o4.w);
        }
    }
}

__device__ __forceinline__ int lbound(const int* __restrict__ a, int key) {
    int lo = 0, hi = N_NODES;
    while (lo < hi) {
        int mid = (lo + hi) >> 1;
        if (a[mid] < key) lo = mid + 1; else hi = mid;
    }
    return lo;
}

// one warp per graph: counts via binary search on sorted batch, mean pool, fc, log_softmax
__global__ void head_kernel(const int* __restrict__ batch,
                            const float* __restrict__ Wfc, const float* __restrict__ bfc,
                            float* __restrict__ out) {
    int g = blockIdx.x;
    int lane = threadIdx.x;
    int lo = lbound(batch, g);
    int hi = lbound(batch, g + 1);
    float cnt = fmaxf((float)(hi - lo), 1.f);
    float pooled = g_sums[g * HC + lane] / cnt;
    float p0 = pooled * Wfc[lane];
    float p1 = pooled * Wfc[HC + lane];
#pragma unroll
    for (int off = 16; off; off >>= 1) {
        p0 += __shfl_xor_sync(0xffffffffu, p0, off);
        p1 += __shfl_xor_sync(0xffffffffu, p1, off);
    }
    if (lane == 0) {
        float l0 = p0 + bfc[0];
        float l1 = p1 + bfc[1];
        float mx = fmaxf(l0, l1);
        float lse = mx + logf(expf(l0 - mx) + expf(l1 - mx));
        out[g * 2 + 0] = l0 - lse;
        out[g * 2 + 1] = l1 - lse;
    }
}

// ---------------- launch ----------------
extern "C" void kernel_launch(void* const* d_in, const int* in_sizes, int n_in,
                              void* d_out, int out_size) {
    const int*   ei        = (const int*)  d_in[0];
    const int*   batch     = (const int*)  d_in[1];
    const float* rand_feat = (const float*)d_in[2];
    const float* W1l  = (const float*)d_in[3];
    const float* b1l  = (const float*)d_in[4];
    const float* W1r  = (const float*)d_in[5];
    const float* b1r  = (const float*)d_in[6];
    const float* att1 = (const float*)d_in[7];
    const float* bias1= (const float*)d_in[8];
    const float* W2l  = (const float*)d_in[9];
    const float* b2l  = (const float*)d_in[10];
    const float* W2r  = (const float*)d_in[11];
    const float* b2r  = (const float*)d_in[12];
    const float* att2 = (const float*)d_in[13];
    const float* bias2= (const float*)d_in[14];
    const float* Wfc  = (const float*)d_in[15];
    const float* bfc  = (const float*)d_in[16];
    float* out = (float*)d_out;

    zero_kernel <<<(N_NODES + 255) / 256, 256>>>();
    build_kernel<<<(E_EDGES / 4 + 255) / 256, 256>>>(ei);

    feat_lin1_kernel<<<(N_NODES * HC + 255) / 256, 256>>>(rand_feat, W1l, b1l, W1r, b1r);

    conv_kernel<0><<<(N_NODES * HC + 255) / 256, 256>>>(
        att1, bias1, W2l, b2l, W2r, b2r, nullptr);
    conv_kernel<1><<<(N_NODES * HC + 255) / 256, 256>>>(
        att2, bias2, nullptr, nullptr, nullptr, nullptr, batch);

    head_kernel<<<G_GRAPHS, 32>>>(batch, Wfc, bfc, out);
}

// round 11
// speedup vs baseline: 1.1067x; 1.0294x over previous
#include <cuda_runtime.h>
#include <math.h>

#define N_NODES 50000
#define E_EDGES 1600000
#define HC      32
#define G_GRAPHS 512
#define STRIDE  96          // padded CSR bucket; indeg ~ Poisson(32), P(>=84) ~ 1e-16

// ---------------- static scratch ----------------
__device__ int   g_cnt   [N_NODES];          // in-degree == bucket fill count
__device__ int   g_outdeg[N_NODES];
__device__ int   g_col   [N_NODES * STRIDE]; // buckets of source ROW OFFSETS (s*HC)
// NOTE: slots >= cnt are stale (0 at load, or prior replay's offsets) — always valid
// row offsets, so unconditional prefetch/gather from them is safe; weights are masked.
__device__ float g_xl [N_NODES * HC];
__device__ float g_xr [N_NODES * HC];
__device__ float g_xl2[N_NODES * HC];
__device__ float g_xr2[N_NODES * HC];
__device__ float g_sums[G_GRAPHS * HC];

__device__ __forceinline__ float ex2(float x) {
    float r; asm("ex2.approx.f32 %0, %1;" : "=f"(r) : "f"(x)); return r;
}

// ---------------- kernels ----------------
__global__ void zero_kernel() {
    int i = blockIdx.x * blockDim.x + threadIdx.x;
    if (i < N_NODES) { g_cnt[i] = 0; g_outdeg[i] = 0; }
    if (i < G_GRAPHS * HC) g_sums[i] = 0.f;
}

// fused CSR build: bucket scatter (pos atomic == indeg count) + outdeg; 4 edges/thread.
// Stores s*HC (row offset) so conv kernels skip the multiply.
__global__ void build_kernel(const int* __restrict__ ei) {
    int e0 = (blockIdx.x * blockDim.x + threadIdx.x) * 4;
    if (e0 >= E_EDGES) return;
    int4 s = *(const int4*)(ei + e0);
    int4 d = *(const int4*)(ei + E_EDGES + e0);
    int p0 = atomicAdd(&g_cnt[d.x], 1);
    int p1 = atomicAdd(&g_cnt[d.y], 1);
    int p2 = atomicAdd(&g_cnt[d.z], 1);
    int p3 = atomicAdd(&g_cnt[d.w], 1);
    g_col[d.x * STRIDE + p0] = s.x * HC;
    g_col[d.y * STRIDE + p1] = s.y * HC;
    g_col[d.z * STRIDE + p2] = s.z * HC;
    g_col[d.w * STRIDE + p3] = s.w * HC;
    atomicAdd(&g_outdeg[s.x], 1); atomicAdd(&g_outdeg[s.y], 1);
    atomicAdd(&g_outdeg[s.z], 1); atomicAdd(&g_outdeg[s.w], 1);
}

// x0 = [1, deg, rand]; xl/xr = x0 @ W^T + b. warp per node, lane = out channel
__global__ void feat_lin1_kernel(const float* __restrict__ rand_feat,
                                 const float* __restrict__ Wl, const float* __restrict__ bl,
                                 const float* __restrict__ Wr, const float* __restrict__ br) {
    int idx = blockIdx.x * blockDim.x + threadIdx.x;
    int node = idx >> 5, lane = idx & 31;
    if (node >= N_NODES) return;
    float x1 = (float)(g_outdeg[node] + g_cnt[node]);
    float x2 = rand_feat[node];
    g_xl[idx] = Wl[lane * 3 + 0] + Wl[lane * 3 + 1] * x1 + Wl[lane * 3 + 2] * x2 + bl[lane];
    g_xr[idx] = Wr[lane * 3 + 0] + Wr[lane * 3 + 1] * x1 + Wr[lane * 3 + 2] * x2 + br[lane];
}

// GATv2 conv: warp per destination node, 4 edge-subgroups of 8 lanes,
// lane holds 4 channels (float4) -> 128B row in ONE LDG.128 per edge.
// Score (log2-scaled): LeakyReLU(m)*att = 0.6*a*(m + (2/3)|m|); a06 = 0.6*log2e*att.
// Sum(a06*xr) hoisted; -pself folded into score seed -> w = ex2(p) direct.
// Edge loop peeled: nfull unconditional 8-edge chunks (no validity checks,
// unconditional prefetch — stale g_col slots are valid offsets) + one masked tail.
// Per-head score reduce = shfl xor 1,2. Cross-subgroup combine = shfl xor 8,16.
// MODE 0: reads g_xl/g_xr, fused 32->32 x2 linear (smem transpose) -> g_xl2/g_xr2.
// MODE 1: reads g_xl2/g_xr2, fused mean-pool atomicAdd into g_sums.
template<int MODE>
__global__ void __launch_bounds__(512, 3)
conv_kernel(const float* __restrict__ att, const float* __restrict__ bias,
            const float* __restrict__ Wl, const float* __restrict__ bl,
            const float* __restrict__ Wr, const float* __restrict__ br,
            const int* __restrict__ batch) {
    const float* __restrict__ xl = (MODE == 0) ? g_xl : g_xl2;
    const float* __restrict__ xr = (MODE == 0) ? g_xr : g_xr2;
    const unsigned FULL = 0xffffffffu;
    const float TWO3 = 0.66666667f;

    __shared__ float sWl[32 * 36];
    __shared__ float sWr[32 * 36];
    __shared__ float so [16 * 32];
    if (MODE == 0) {
        for (int i = threadIdx.x; i < 1024; i += blockDim.x) {
            int r = i >> 5, c = i & 31;
            sWl[r * 36 + c] = Wl[i];
            sWr[r * 36 + c] = Wr[i];
        }
        __syncthreads();
    }
    int gidx = blockIdx.x * blockDim.x + threadIdx.x;
    int node = gidx >> 5, lane = gidx & 31;
    if (node >= N_NODES) return;
    const int sub = lane >> 3;     // edge slot 0..3
    const int q   = lane & 7;      // channel quad 0..7
    const int wlocal = (threadIdx.x >> 5);
    const int nodeHC = node * HC;

    const float LOG2E = 1.4426950408889634f;
    float4 a06 = *(const float4*)(att + q * 4);
    a06.x *= 0.6f * LOG2E; a06.y *= 0.6f * LOG2E;
    a06.z *= 0.6f * LOG2E; a06.w *= 0.6f * LOG2E;

    const float4 xr4 = *(const float4*)(xr + nodeHC + q * 4);
    // hoisted per-node term: sum_c a06_c * xr_c (this lane's 4 channels)
    float base = a06.x * xr4.x + a06.y * xr4.y + a06.z * xr4.z + a06.w * xr4.w;

    // self loop + softmax baseline pself (log2-scaled, per head)
    const float4 vs4 = *(const float4*)(xl + nodeHC + q * 4);
    float ps = base, m, u;
    m = vs4.x + xr4.x; u = fmaf(TWO3, fabsf(m), vs4.x); ps = fmaf(a06.x, u, ps);
    m = vs4.y + xr4.y; u = fmaf(TWO3, fabsf(m), vs4.y); ps = fmaf(a06.y, u, ps);
    m = vs4.z + xr4.z; u = fmaf(TWO3, fabsf(m), vs4.z); ps = fmaf(a06.z, u, ps);
    m = vs4.w + xr4.w; u = fmaf(TWO3, fabsf(m), vs4.w); ps = fmaf(a06.w, u, ps);
    ps += __shfl_xor_sync(FULL, ps, 1);
    ps += __shfl_xor_sync(FULL, ps, 2);
    // fold base and -pself/4 into the per-edge score seed
    const float seed = base - 0.25f * ps;

    float wsf = (sub == 0) ? 1.f : 0.f;   // self weight: ex2(ps - ps) = 1
    float denom = wsf;
    float4 acc = make_float4(vs4.x * wsf, vs4.y * wsf, vs4.z * wsf, vs4.w * wsf);

    const int cnt = g_cnt[node];
    const int* colp = g_col + node * STRIDE;
    const int nfull = cnt >> 3;
    const int rem   = cnt & 7;

    // unconditional prefetch; max index read anywhere is nfull*8+11 <= cnt+11 < STRIDE
    int c0 = __ldg(colp + sub);
    int c1 = __ldg(colp + 4 + sub);

    for (int it = 0; it < nfull; it++) {
        int s0 = c0, s1 = c1;
        colp += 8;
        c0 = __ldg(colp + sub);
        c1 = __ldg(colp + 4 + sub);

        float4 a0 = *(const float4*)(xl + s0 + q * 4);
        float4 a1 = *(const float4*)(xl + s1 + q * 4);

        float p0 = seed, p1 = seed, t, v;
        t = a0.x + xr4.x; v = fmaf(TWO3, fabsf(t), a0.x); p0 = fmaf(a06.x, v, p0);
        t = a0.y + xr4.y; v = fmaf(TWO3, fabsf(t), a0.y); p0 = fmaf(a06.y, v, p0);
        t = a0.z + xr4.z; v = fmaf(TWO3, fabsf(t), a0.z); p0 = fmaf(a06.z, v, p0);
        t = a0.w + xr4.w; v = fmaf(TWO3, fabsf(t), a0.w); p0 = fmaf(a06.w, v, p0);
        t = a1.x + xr4.x; v = fmaf(TWO3, fabsf(t), a1.x); p1 = fmaf(a06.x, v, p1);
        t = a1.y + xr4.y; v = fmaf(TWO3, fabsf(t), a1.y); p1 = fmaf(a06.y, v, p1);
        t = a1.z + xr4.z; v = fmaf(TWO3, fabsf(t), a1.z); p1 = fmaf(a06.z, v, p1);
        t = a1.w + xr4.w; v = fmaf(TWO3, fabsf(t), a1.w); p1 = fmaf(a06.w, v, p1);

        p0 += __shfl_xor_sync(FULL, p0, 1);
        p0 += __shfl_xor_sync(FULL, p0, 2);
        p1 += __shfl_xor_sync(FULL, p1, 1);
        p1 += __shfl_xor_sync(FULL, p1, 2);
        float w0 = ex2(p0);
        float w1 = ex2(p1);
        denom += w0 + w1;
        acc.x = fmaf(w0, a0.x, acc.x); acc.y = fmaf(w0, a0.y, acc.y);
        acc.z = fmaf(w0, a0.z, acc.z); acc.w = fmaf(w0, a0.w, acc.w);
        acc.x = fmaf(w1, a1.x, acc.x); acc.y = fmaf(w1, a1.y, acc.y);
        acc.z = fmaf(w1, a1.z, acc.z); acc.w = fmaf(w1, a1.w, acc.w);
    }

    if (rem) {
        // tail: stale-slot gathers are valid addresses; weights masked to 0
        int s0 = c0, s1 = c1;
        float4 a0 = *(const float4*)(xl + s0 + q * 4);
        float4 a1 = *(const float4*)(xl + s1 + q * 4);

        float p0 = seed, p1 = seed, t, v;
        t = a0.x + xr4.x; v = fmaf(TWO3, fabsf(t), a0.x); p0 = fmaf(a06.x, v, p0);
        t = a0.y + xr4.y; v = fmaf(TWO3, fabsf(t), a0.y); p0 = fmaf(a06.y, v, p0);
        t = a0.z + xr4.z; v = fmaf(TWO3, fabsf(t), a0.z); p0 = fmaf(a06.z, v, p0);
        t = a0.w + xr4.w; v = fmaf(TWO3, fabsf(t), a0.w); p0 = fmaf(a06.w, v, p0);
        t = a1.x + xr4.x; v = fmaf(TWO3, fabsf(t), a1.x); p1 = fmaf(a06.x, v, p1);
        t = a1.y + xr4.y; v = fmaf(TWO3, fabsf(t), a1.y); p1 = fmaf(a06.y, v, p1);
        t = a1.z + xr4.z; v = fmaf(TWO3, fabsf(t), a1.z); p1 = fmaf(a06.z, v, p1);
        t = a1.w + xr4.w; v = fmaf(TWO3, fabsf(t), a1.w); p1 = fmaf(a06.w, v, p1);

        p0 += __shfl_xor_sync(FULL, p0, 1);
        p0 += __shfl_xor_sync(FULL, p0, 2);
        p1 += __shfl_xor_sync(FULL, p1, 1);
        p1 += __shfl_xor_sync(FULL, p1, 2);
        float w0 = (sub     < rem) ? ex2(p0) : 0.f;
        float w1 = (sub + 4 < rem) ? ex2(p1) : 0.f;
        denom += w0 + w1;
        acc.x = fmaf(w0, a0.x, acc.x); acc.y = fmaf(w0, a0.y, acc.y);
        acc.z = fmaf(w0, a0.z, acc.z); acc.w = fmaf(w0, a0.w, acc.w);
        acc.x = fmaf(w1, a1.x, acc.x); acc.y = fmaf(w1, a1.y, acc.y);
        acc.z = fmaf(w1, a1.z, acc.z); acc.w = fmaf(w1, a1.w, acc.w);
    }

    // combine the 4 edge subgroups (q invariant under xor 8/16 -> head-safe)
#pragma unroll
    for (int off = 8; off <= 16; off <<= 1) {
        acc.x += __shfl_xor_sync(FULL, acc.x, off);
        acc.y += __shfl_xor_sync(FULL, acc.y, off);
        acc.z += __shfl_xor_sync(FULL, acc.z, off);
        acc.w += __shfl_xor_sync(FULL, acc.w, off);
        denom += __shfl_xor_sync(FULL, denom, off);
    }

    const float4 b4 = *(const float4*)(bias + q * 4);
    float rd = __fdividef(1.f, denom + 1e-16f);
    float4 o4;
    o4.x = fmaf(acc.x, rd, b4.x);
    o4.y = fmaf(acc.y, rd, b4.y);
    o4.z = fmaf(acc.z, rd, b4.z);
    o4.w = fmaf(acc.w, rd, b4.w);
    o4.x = o4.x > 0.f ? o4.x : (__expf(o4.x) - 1.f);
    o4.y = o4.y > 0.f ? o4.y : (__expf(o4.y) - 1.f);
    o4.z = o4.z > 0.f ? o4.z : (__expf(o4.z) - 1.f);
    o4.w = o4.w > 0.f ? o4.w : (__expf(o4.w) - 1.f);

    if (MODE == 0) {
        // fused lin2 via warp-private smem transpose (no shuffles)
        if (sub == 0) *(float4*)&so[wlocal * 32 + q * 4] = o4;
        __syncwarp(FULL);
        float aL = bl[lane], aR = br[lane];
#pragma unroll
        for (int ch = 0; ch < 8; ch++) {
            float4 ov = *(const float4*)&so[wlocal * 32 + ch * 4];   // broadcast
            float4 wl = *(const float4*)&sWl[lane * 36 + ch * 4];    // conflict-free
            float4 wr = *(const float4*)&sWr[lane * 36 + ch * 4];
            aL = fmaf(ov.x, wl.x, aL); aL = fmaf(ov.y, wl.y, aL);
            aL = fmaf(ov.z, wl.z, aL); aL = fmaf(ov.w, wl.w, aL);
            aR = fmaf(ov.x, wr.x, aR); aR = fmaf(ov.y, wr.y, aR);
            aR = fmaf(ov.z, wr.z, aR); aR = fmaf(ov.w, wr.w, aR);
        }
        g_xl2[nodeHC + lane] = aL;
        g_xr2[nodeHC + lane] = aR;
    } else {
        if (sub == 0) {
            int g = batch[node];
            float* dst = &g_sums[g * HC + q * 4];
            atomicAdd(dst + 0, o4.x);
            atomicAdd(dst + 1, o4.y);
            atomicAdd(dst + 2, o4.z);
            atomicAdd(dst + 3, o4.w);
        }
    }
}

__device__ __forceinline__ int lbound(const int* __restrict__ a, int key) {
    int lo = 0, hi = N_NODES;
    while (lo < hi) {
        int mid = (lo + hi) >> 1;
        if (a[mid] < key) lo = mid + 1; else hi = mid;
    }
    return lo;
}

// one warp per graph: counts via binary search on sorted batch, mean pool, fc, log_softmax
__global__ void head_kernel(const int* __restrict__ batch,
                            const float* __restrict__ Wfc, const float* __restrict__ bfc,
                            float* __restrict__ out) {
    int g = blockIdx.x;
    int lane = threadIdx.x;
    int lo = lbound(batch, g);
    int hi = lbound(batch, g + 1);
    float cnt = fmaxf((float)(hi - lo), 1.f);
    float pooled = g_sums[g * HC + lane] / cnt;
    float p0 = pooled * Wfc[lane];
    float p1 = pooled * Wfc[HC + lane];
#pragma unroll
    for (int off = 16; off; off >>= 1) {
        p0 += __shfl_xor_sync(0xffffffffu, p0, off);
        p1 += __shfl_xor_sync(0xffffffffu, p1, off);
    }
    if (lane == 0) {
        float l0 = p0 + bfc[0];
        float l1 = p1 + bfc[1];
        float mx = fmaxf(l0, l1);
        float lse = mx + logf(expf(l0 - mx) + expf(l1 - mx));
        out[g * 2 + 0] = l0 - lse;
        out[g * 2 + 1] = l1 - lse;
    }
}

// ---------------- launch ----------------
extern "C" void kernel_launch(void* const* d_in, const int* in_sizes, int n_in,
                              void* d_out, int out_size) {
    const int*   ei        = (const int*)  d_in[0];
    const int*   batch     = (const int*)  d_in[1];
    const float* rand_feat = (const float*)d_in[2];
    const float* W1l  = (const float*)d_in[3];
    const float* b1l  = (const float*)d_in[4];
    const float* W1r  = (const float*)d_in[5];
    const float* b1r  = (const float*)d_in[6];
    const float* att1 = (const float*)d_in[7];
    const float* bias1= (const float*)d_in[8];
    const float* W2l  = (const float*)d_in[9];
    const float* b2l  = (const float*)d_in[10];
    const float* W2r  = (const float*)d_in[11];
    const float* b2r  = (const float*)d_in[12];
    const float* att2 = (const float*)d_in[13];
    const float* bias2= (const float*)d_in[14];
    const float* Wfc  = (const float*)d_in[15];
    const float* bfc  = (const float*)d_in[16];
    float* out = (float*)d_out;

    zero_kernel <<<(N_NODES + 255) / 256, 256>>>();
    build_kernel<<<(E_EDGES / 4 + 255) / 256, 256>>>(ei);

    feat_lin1_kernel<<<(N_NODES * HC + 255) / 256, 256>>>(rand_feat, W1l, b1l, W1r, b1r);

    conv_kernel<0><<<(N_NODES * HC + 511) / 512, 512>>>(
        att1, bias1, W2l, b2l, W2r, b2r, nullptr);
    conv_kernel<1><<<(N_NODES * HC + 511) / 512, 512>>>(
        att2, bias2, nullptr, nullptr, nullptr, nullptr, batch);

    head_kernel<<<G_GRAPHS, 32>>>(batch, Wfc, bfc, out);
}